// round 14
// baseline (speedup 1.0000x reference)
#include <cuda_runtime.h>
#include <math.h>

#define BATCH 4
#define SEQ   2048
#define DIMN  1024
#define HEADS 16
#define DHEAD 64
#define ROWS  (BATCH*SEQ)      /* 8192 */
#define QKV_N (3*DIMN)         /* 3072 */

// Scratch (allocation-free rule: __device__ globals)
static __device__ float g_xn[(size_t)ROWS*DIMN];
static __device__ float g_qkv[(size_t)ROWS*QKV_N];   // K cols perm8'd, V cols perm16'd
static __device__ float g_attn[(size_t)ROWS*DIMN];
static __device__ float g_wq[(size_t)DIMN*QKV_N];
static __device__ float g_wo[(size_t)DIMN*DIMN];
// progress counters (decoupled lookback between fused stages)
static __device__ int   g_cnt1[64];   // qkv row-tiles (128 rows): target 24
static __device__ int   g_cnt2[64];   // attn row-tiles (128 rows): target 16

// ---------------------------------------------------------------------------
__device__ __forceinline__ unsigned f2tf(float x) {
    unsigned r;
    asm("cvt.rna.tf32.f32 %0, %1;" : "=r"(r) : "f"(x));
    return r;
}

__device__ __forceinline__ float fex2(float x) {   // 2^x, clamped below
    float r;
    x = fmaxf(x, -126.f);
    asm("ex2.approx.ftz.f32 %0, %1;" : "=f"(r) : "f"(x));
    return r;
}

__device__ __forceinline__ int permcol(int c) {
    int reg = c >> 10;
    if (reg == 1) return (c & ~7)  | ((c & 3) << 1) | ((c >> 2) & 1);
    if (reg == 2) return (c & ~15) | ((c & 7) << 1) | ((c >> 3) & 1);
    return c;
}

__device__ __forceinline__ void mma_tf32(float& c0, float& c1, float& c2, float& c3,
                                         unsigned a0, unsigned a1, unsigned a2, unsigned a3,
                                         unsigned b0, unsigned b1) {
    asm volatile(
        "mma.sync.aligned.m16n8k8.row.col.f32.tf32.tf32.f32 "
        "{%0,%1,%2,%3}, {%4,%5,%6,%7}, {%8,%9}, {%0,%1,%2,%3};\n"
        : "+f"(c0), "+f"(c1), "+f"(c2), "+f"(c3)
        : "r"(a0), "r"(a1), "r"(a2), "r"(a3), "r"(b0), "r"(b1));
}

#define CP_ASYNC16(dst, src) \
    asm volatile("cp.async.cg.shared.global [%0], [%1], 16;\n" :: "r"(dst), "l"(src))

// classic flag wait: producer did __threadfence()+atomicAdd (release);
// consumer polls volatile then __threadfence() (acquire).
__device__ __forceinline__ void waitcnt(const int* c, int target) {
    if (*(volatile const int*)c < target) {
        while (*(volatile const int*)c < target) __nanosleep(128);
    }
    __threadfence();
}

// ---------------------------------------------------------------------------
// prep: zero counters + wq cvt (blocks 0..3071) + wo cvt + ln
// (separate kernel: its completion, via PDL GridDepSync, orders the counter
//  reset before any fused CTA — required for graph-replay safety)
// ---------------------------------------------------------------------------
#define PREP_WQ_BLKS 3072
#define PREP_WO_BLKS 1024
#define PREP_BLKS    (PREP_WQ_BLKS + PREP_WO_BLKS + ROWS)

__global__ __launch_bounds__(256) void prep_kernel(const float* __restrict__ w_qkv,
                                                   const float* __restrict__ w_out,
                                                   const float* __restrict__ x,
                                                   const float* __restrict__ gamma,
                                                   const float* __restrict__ beta) {
    cudaTriggerProgrammaticLaunchCompletion();
    const int blk = blockIdx.x;
    const int t = threadIdx.x;

    if (blk == 0 && t < 64) { g_cnt1[t] = 0; g_cnt2[t] = 0; }

    if (blk < PREP_WQ_BLKS + PREP_WO_BLKS) {
        const float* src = (blk < PREP_WQ_BLKS) ? w_qkv : w_out;
        float* dst       = (blk < PREP_WQ_BLKS) ? g_wq  : g_wo;
        int i = (blk < PREP_WQ_BLKS ? blk : blk - PREP_WQ_BLKS) * 256 + t;
        float4 v = ((const float4*)src)[i];
        uint4 o;
        o.x = f2tf(v.x); o.y = f2tf(v.y); o.z = f2tf(v.z); o.w = f2tf(v.w);
        ((uint4*)dst)[i] = o;
        return;
    }

    __shared__ float red[16];
    const int row = blk - (PREP_WQ_BLKS + PREP_WO_BLKS);
    const float* xr = x + (size_t)row * DIMN;
    float4 v = *(const float4*)(xr + t * 4);
    float s = v.x + v.y + v.z + v.w;
    float q = v.x*v.x + v.y*v.y + v.z*v.z + v.w*v.w;
    #pragma unroll
    for (int o = 16; o; o >>= 1) {
        s += __shfl_xor_sync(0xffffffffu, s, o);
        q += __shfl_xor_sync(0xffffffffu, q, o);
    }
    if ((t & 31) == 0) { red[t >> 5] = s; red[8 + (t >> 5)] = q; }
    __syncthreads();
    if (t < 32) {
        float ss = (t < 8) ? red[t] : 0.f;
        float qq = (t < 8) ? red[8 + t] : 0.f;
        #pragma unroll
        for (int o = 4; o; o >>= 1) {
            ss += __shfl_xor_sync(0xffffffffu, ss, o);
            qq += __shfl_xor_sync(0xffffffffu, qq, o);
        }
        if (t == 0) { red[0] = ss; red[1] = qq; }
    }
    __syncthreads();
    const float mean = red[0] * (1.f / DIMN);
    const float var  = red[1] * (1.f / DIMN) - mean * mean;
    const float inv  = rsqrtf(var + 1e-5f);
    float4 g = *(const float4*)(gamma + t * 4);
    float4 b = *(const float4*)(beta  + t * 4);
    uint4 o4;
    o4.x = f2tf((v.x - mean) * inv * g.x + b.x);
    o4.y = f2tf((v.y - mean) * inv * g.y + b.y);
    o4.z = f2tf((v.z - mean) * inv * g.z + b.z);
    o4.w = f2tf((v.w - mean) * inv * g.w + b.w);
    *(uint4*)(g_xn + (size_t)row * DIMN + t * 4) = o4;
}

// ---------------------------------------------------------------------------
// GEMM body (R13, proven): 3-stage cp.async pipeline, one barrier per K-tile.
// ---------------------------------------------------------------------------
#define ASTR 36
#define BSTR 136
#define ABUF (128*ASTR)
#define BBUF (32*BSTR)
#define STG  (ABUF+BBUF)

__device__ __forceinline__ void gemm_body(const float* __restrict__ A,
                                          const float* __restrict__ B,
                                          const float* __restrict__ bias,
                                          float* __restrict__ C,
                                          int N, int K, int mode,
                                          int bm, int bn, float* sm) {
    const int tid = threadIdx.x;
    const int wid = tid >> 5, lane = tid & 31;
    const int g = lane >> 2, tg = lane & 3;
    const int wm = wid >> 1, wn = wid & 1;

    float c[2][8][4] = {};

    auto loadAB = [&](int buf, int k0) {
        float* As = sm + buf * STG;
        float* Bs = As + ABUF;
        unsigned abase = (unsigned)__cvta_generic_to_shared(As);
        unsigned bbase = (unsigned)__cvta_generic_to_shared(Bs);
        #pragma unroll
        for (int p = 0; p < 4; p++) {
            int idx = tid + p * 256;
            int ar = idx >> 3, ac = (idx & 7) * 4;
            CP_ASYNC16(abase + (ar * ASTR + ac) * 4, A + (size_t)(bm + ar) * K + k0 + ac);
            int br = idx >> 5, bc = (idx & 31) * 4;
            CP_ASYNC16(bbase + (br * BSTR + bc) * 4, B + (size_t)(k0 + br) * N + bn + bc);
        }
    };

    const int nk = K / 32;
    loadAB(0, 0);
    asm volatile("cp.async.commit_group;\n");
    loadAB(1, 32);
    asm volatile("cp.async.commit_group;\n");

    int cur = 0, nxt = 2;
    for (int kb = 0; kb < nk; kb++) {
        if (kb + 1 < nk) {
            asm volatile("cp.async.wait_group 1;\n");
        } else {
            asm volatile("cp.async.wait_group 0;\n");
        }
        __syncthreads();
        if (kb + 2 < nk) {
            loadAB(nxt, (kb + 2) * 32);
            asm volatile("cp.async.commit_group;\n");
        }

        const float* Ab = sm + cur * STG;
        const float* Bb = Ab + ABUF;
        #pragma unroll
        for (int ks = 0; ks < 4; ks++) {
            const int kk = ks * 8;
            unsigned a[2][4], b[8][2];
            #pragma unroll
            for (int mt = 0; mt < 2; mt++) {
                int r0 = wm * 32 + mt * 16;
                a[mt][0] = __float_as_uint(Ab[(r0 + g)     * ASTR + kk + tg]);
                a[mt][1] = __float_as_uint(Ab[(r0 + g + 8) * ASTR + kk + tg]);
                a[mt][2] = __float_as_uint(Ab[(r0 + g)     * ASTR + kk + tg + 4]);
                a[mt][3] = __float_as_uint(Ab[(r0 + g + 8) * ASTR + kk + tg + 4]);
            }
            #pragma unroll
            for (int nt = 0; nt < 8; nt++) {
                int col = wn * 64 + nt * 8 + g;
                b[nt][0] = __float_as_uint(Bb[(kk + tg)     * BSTR + col]);
                b[nt][1] = __float_as_uint(Bb[(kk + tg + 4) * BSTR + col]);
            }
            #pragma unroll
            for (int mt = 0; mt < 2; mt++)
                #pragma unroll
                for (int nt = 0; nt < 8; nt++)
                    mma_tf32(c[mt][nt][0], c[mt][nt][1], c[mt][nt][2], c[mt][nt][3],
                             a[mt][0], a[mt][1], a[mt][2], a[mt][3],
                             b[nt][0], b[nt][1]);
        }
        cur = (cur == 2) ? 0 : cur + 1;
        nxt = (nxt == 2) ? 0 : nxt + 1;
    }

    #pragma unroll
    for (int mt = 0; mt < 2; mt++) {
        int r0 = bm + wm * 32 + mt * 16 + g;
        #pragma unroll
        for (int nt = 0; nt < 8; nt++) {
            int col = bn + wn * 64 + nt * 8 + 2 * tg;
            if (mode == 0) {
                float b0 = bias ? bias[col] : 0.f, b1 = bias ? bias[col + 1] : 0.f;
                *(float2*)(C + (size_t)r0 * N + col) =
                    make_float2(c[mt][nt][0] + b0, c[mt][nt][1] + b1);
                *(float2*)(C + (size_t)(r0 + 8) * N + col) =
                    make_float2(c[mt][nt][2] + b0, c[mt][nt][3] + b1);
            } else {
                int c0 = permcol(col), c1 = permcol(col + 1);
                C[(size_t)r0 * N + c0]       = __uint_as_float(f2tf(c[mt][nt][0]));
                C[(size_t)r0 * N + c1]       = __uint_as_float(f2tf(c[mt][nt][1]));
                C[(size_t)(r0 + 8) * N + c0] = __uint_as_float(f2tf(c[mt][nt][2]));
                C[(size_t)(r0 + 8) * N + c1] = __uint_as_float(f2tf(c[mt][nt][3]));
            }
        }
    }
}

// ---------------------------------------------------------------------------
// Flash body (R13, proven) with per-tile producer waits on g_cnt1.
// ---------------------------------------------------------------------------
#define FSK 72
#define FSV 72
#define FSP 68
#define KBUF (64*FSK)
#define VBUF (64*FSV)
#define FL_SMF (2*KBUF + 2*VBUF + 128*FSP)    /* 27136 floats = 108544 B */

__device__ __forceinline__ void flash_body(int qt, int b, int h, float* sm) {
    float* Ks = sm;
    float* Vs = sm + 2 * KBUF;
    float* Ps = sm + 2 * KBUF + 2 * VBUF;

    const int tid = threadIdx.x;
    const int wid = tid >> 5, lane = tid & 31;
    const int g = lane >> 2, tg = lane & 3;
    const int qr = wid * 16;
    const size_t base = (size_t)b * SEQ;
    const int qoff = h * DHEAD;
    const int koff = DIMN + h * DHEAD;
    const int voff = 2 * DIMN + h * DHEAD;
    const float* qkv = g_qkv;
    const int ct0 = b * 16;

    waitcnt(&g_cnt1[ct0 + qt], 24);
    #pragma unroll
    for (int p = 0; p < 8; p++) {
        int idx = tid + p * 256;
        int row = idx >> 4, c4 = (idx & 15) * 4;
        *(float4*)(Ps + row * FSP + c4) =
            *(const float4*)(qkv + (base + qt * 128 + row) * QKV_N + qoff + c4);
    }
    __syncthreads();
    unsigned qf[8][4];
    {
        const float QS = 0.125f * 1.4426950408889634f;
        const int r0 = (qr + g) * FSP, r1 = (qr + g + 8) * FSP;
        #pragma unroll
        for (int ks = 0; ks < 8; ks++) {
            int c = ks * 8 + tg;
            qf[ks][0] = f2tf(Ps[r0 + c]     * QS);
            qf[ks][1] = f2tf(Ps[r1 + c]     * QS);
            qf[ks][2] = f2tf(Ps[r0 + c + 4] * QS);
            qf[ks][3] = f2tf(Ps[r1 + c + 4] * QS);
        }
    }

    auto loadKV = [&](int buf, int kt) {
        unsigned kbase = (unsigned)__cvta_generic_to_shared(Ks + buf * KBUF);
        unsigned vbase = (unsigned)__cvta_generic_to_shared(Vs + buf * VBUF);
        #pragma unroll
        for (int p = 0; p < 4; p++) {
            int idx = tid + p * 256;
            int row = idx >> 4, c4 = (idx & 15) * 4;
            const float* rp = qkv + (base + kt * 64 + row) * QKV_N;
            CP_ASYNC16(kbase + (row * FSK + c4) * 4, rp + koff + c4);
            CP_ASYNC16(vbase + (row * FSV + c4) * 4, rp + voff + c4);
        }
    };

    int kvw = -1;
    auto wait_kv = [&](int j) {
        if (j > kvw) { waitcnt(&g_cnt1[ct0 + j], 24); kvw = j; }
    };

    float l[2] = {0.f, 0.f};
    float c[4][2][4] = {};

    const int NT = SEQ / 64;
    wait_kv(0);
    loadKV(0, 0);
    asm volatile("cp.async.commit_group;\n");

    for (int kt = 0; kt < NT; kt++) {
        asm volatile("cp.async.wait_group 0;\n");
        __syncthreads();
        if (kt + 1 < NT) {
            wait_kv((kt + 1) >> 1);
            loadKV((kt + 1) & 1, kt + 1);
            asm volatile("cp.async.commit_group;\n");
        }

        const float* Kb = Ks + (kt & 1) * KBUF;
        const float* Vb = Vs + (kt & 1) * VBUF;

        float sc[8][4] = {};
        #pragma unroll
        for (int ks = 0; ks < 8; ks++) {
            const int kk = ks * 8;
            #pragma unroll
            for (int nt = 0; nt < 8; nt++) {
                float2 bb = *(const float2*)&Kb[(nt * 8 + g) * FSK + kk + 2 * tg];
                mma_tf32(sc[nt][0], sc[nt][1], sc[nt][2], sc[nt][3],
                         qf[ks][0], qf[ks][1], qf[ks][2], qf[ks][3],
                         __float_as_uint(bb.x), __float_as_uint(bb.y));
            }
        }

        #pragma unroll
        for (int rh = 0; rh < 2; rh++) {
            float rs = 0.f;
            int prow = (qr + g + 8 * rh) * FSP;
            #pragma unroll
            for (int nt = 0; nt < 8; nt++) {
                float p0 = __uint_as_float(f2tf(fex2(sc[nt][2 * rh])));
                float p1 = __uint_as_float(f2tf(fex2(sc[nt][2 * rh + 1])));
                rs += p0 + p1;
                *(float2*)(Ps + prow + nt * 8 + 2 * tg) = make_float2(p0, p1);
            }
            rs += __shfl_xor_sync(0xffffffffu, rs, 1);
            rs += __shfl_xor_sync(0xffffffffu, rs, 2);
            l[rh] += rs;
        }
        __syncwarp();

        #pragma unroll
        for (int ks = 0; ks < 8; ks++) {
            const int kk = ks * 8;
            unsigned pb[2][2];
            #pragma unroll
            for (int nh = 0; nh < 2; nh++) {
                pb[nh][0] = __float_as_uint(Ps[(qr + nh * 8 + g) * FSP + kk + tg]);
                pb[nh][1] = __float_as_uint(Ps[(qr + nh * 8 + g) * FSP + kk + tg + 4]);
            }
            #pragma unroll
            for (int mt = 0; mt < 4; mt++) {
                float2 va0 = *(const float2*)&Vb[(kk + tg)     * FSV + mt * 16 + 2 * g];
                float2 va1 = *(const float2*)&Vb[(kk + tg + 4) * FSV + mt * 16 + 2 * g];
                #pragma unroll
                for (int nh = 0; nh < 2; nh++)
                    mma_tf32(c[mt][nh][0], c[mt][nh][1], c[mt][nh][2], c[mt][nh][3],
                             __float_as_uint(va0.x), __float_as_uint(va0.y),
                             __float_as_uint(va1.x), __float_as_uint(va1.y),
                             pb[nh][0], pb[nh][1]);
            }
        }
        __syncwarp();
    }

    float linv[2][2];
    #pragma unroll
    for (int nh = 0; nh < 2; nh++) {
        linv[nh][0] = 1.f / __shfl_sync(0xffffffffu, l[nh], 8 * tg);
        linv[nh][1] = 1.f / __shfl_sync(0xffffffffu, l[nh], 8 * tg + 4);
    }
    #pragma unroll
    for (int mt = 0; mt < 4; mt++) {
        #pragma unroll
        for (int nh = 0; nh < 2; nh++) {
            int q = qt * 128 + qr + nh * 8 + 2 * tg;
            int d0 = mt * 16 + g;
            size_t ro = (base + q) * (size_t)DIMN + h * DHEAD;
            g_attn[ro + d0]            = __uint_as_float(f2tf(c[mt][nh][0] * linv[nh][0]));
            g_attn[ro + DIMN + d0]     = __uint_as_float(f2tf(c[mt][nh][1] * linv[nh][1]));
            g_attn[ro + d0 + 8]        = __uint_as_float(f2tf(c[mt][nh][2] * linv[nh][0]));
            g_attn[ro + DIMN + d0 + 8] = __uint_as_float(f2tf(c[mt][nh][3] * linv[nh][1]));
        }
    }
}

// ---------------------------------------------------------------------------
// Fused kernel, batch-interleaved dispatch:
//   g1b0 flb0 g1b1 flb1 g2b0 g1b2 flb2 g2b1 g1b3 flb3 g2b2 g2b3
// Every wait references a strictly earlier segment -> deadlock-free.
// ---------------------------------------------------------------------------
#define SEG_G1 384   /* gemm1 CTAs per batch: 16 row-tiles x 24 col-tiles */
#define SEG_FL 256   /* flash CTAs per batch: 16 q-tiles x 16 heads */
#define SEG_G2 128   /* gemm2 CTAs per batch: 16 row-tiles x 8 col-tiles */
#define FUSED_BLKS 3072
#define FUSED_SMEM 108544

__global__ __launch_bounds__(256, 2) void fused_kernel(const float* __restrict__ b_out,
                                                       float* __restrict__ out) {
    extern __shared__ float sm[];
    cudaGridDependencySynchronize();       // prep done (xn, weights, counters=0)
    cudaTriggerProgrammaticLaunchCompletion();

    const int bid = blockIdx.x;
    const int tid = threadIdx.x;

    // segment table: {stage, batch, local_offset_base}
    // offsets: 0 g1b0 | 384 flb0 | 640 g1b1 | 1024 flb1 | 1280 g2b0 | 1408 g1b2
    //        | 1792 flb2 | 2048 g2b1 | 2176 g1b3 | 2560 flb3 | 2816 g2b2 | 2944 g2b3
    int stage, b, loc;
    if      (bid < 384)  { stage = 0; b = 0; loc = bid; }
    else if (bid < 640)  { stage = 1; b = 0; loc = bid - 384; }
    else if (bid < 1024) { stage = 0; b = 1; loc = bid - 640; }
    else if (bid < 1280) { stage = 1; b = 1; loc = bid - 1024; }
    else if (bid < 1408) { stage = 2; b = 0; loc = bid - 1280; }
    else if (bid < 1792) { stage = 0; b = 2; loc = bid - 1408; }
    else if (bid < 2048) { stage = 1; b = 2; loc = bid - 1792; }
    else if (bid < 2176) { stage = 2; b = 1; loc = bid - 2048; }
    else if (bid < 2560) { stage = 0; b = 3; loc = bid - 2176; }
    else if (bid < 2816) { stage = 1; b = 3; loc = bid - 2560; }
    else if (bid < 2944) { stage = 2; b = 2; loc = bid - 2816; }
    else                 { stage = 2; b = 3; loc = bid - 2944; }

    if (stage == 0) {
        // gemm1: row-tile-major within the batch so qkv tiles complete in order
        const int bm = (b * 16 + loc / 24) * 128, bn = (loc % 24) * 128;
        gemm_body(g_xn, g_wq, nullptr, g_qkv, QKV_N, DIMN, 1, bm, bn, sm);
        __syncthreads();
        if (tid == 0) { __threadfence(); atomicAdd(&g_cnt1[bm >> 7], 1); }
    } else if (stage == 1) {
        // flash: qt-major, head fastest
        const int qt = loc >> 4, h = loc & 15;
        flash_body(qt, b, h, sm);
        __syncthreads();
        if (tid == 0) { __threadfence(); atomicAdd(&g_cnt2[b * 16 + qt], 1); }
    } else {
        // gemm2: row-tile-major; waits for all 16 heads of its attn row-tile
        const int bm = (b * 16 + (loc >> 3)) * 128, bn = (loc & 7) * 128;
        waitcnt(&g_cnt2[bm >> 7], 16);
        gemm_body(g_attn, g_wo, b_out, out, DIMN, DIMN, 0, bm, bn, sm);
    }
}

// ---------------------------------------------------------------------------
extern "C" void kernel_launch(void* const* d_in, const int* in_sizes, int n_in,
                              void* d_out, int out_size)
{
    const float* x      = (const float*)d_in[0];
    const float* gamma  = (const float*)d_in[1];
    const float* beta   = (const float*)d_in[2];
    const float* w_qkv  = (const float*)d_in[3];
    const float* w_out  = (const float*)d_in[4];
    const float* b_out  = (const float*)d_in[5];
    float* out = (float*)d_out;

    cudaFuncSetAttribute(fused_kernel, cudaFuncAttributeMaxDynamicSharedMemorySize,
                         FUSED_SMEM);

    cudaLaunchAttribute pdl[1];
    pdl[0].id = cudaLaunchAttributeProgrammaticStreamSerialization;
    pdl[0].val.programmaticStreamSerializationAllowed = 1;

    prep_kernel<<<PREP_BLKS, 256>>>(w_qkv, w_out, x, gamma, beta);

    cudaLaunchConfig_t cfg = {};
    cfg.gridDim = dim3(FUSED_BLKS);
    cfg.blockDim = dim3(256);
    cfg.dynamicSmemBytes = FUSED_SMEM;
    cfg.stream = 0;
    cfg.attrs = pdl;
    cfg.numAttrs = 1;
    cudaLaunchKernelEx(&cfg, fused_kernel, b_out, out);
}

// round 15
// speedup vs baseline: 1.0382x; 1.0382x over previous
#include <cuda_runtime.h>
#include <math.h>

#define BATCH 4
#define SEQ   2048
#define DIMN  1024
#define HEADS 16
#define DHEAD 64
#define ROWS  (BATCH*SEQ)      /* 8192 */
#define QKV_N (3*DIMN)         /* 3072 */

// Scratch (allocation-free rule: __device__ globals)
static __device__ float g_xn[(size_t)ROWS*DIMN];
static __device__ float g_qkv[(size_t)ROWS*QKV_N];   // K cols perm8'd, V cols perm16'd
static __device__ float g_attn[(size_t)ROWS*DIMN];
static __device__ float g_wq[(size_t)DIMN*QKV_N];
static __device__ float g_wo[(size_t)DIMN*DIMN];
// progress counters (decoupled lookback between fused stages)
static __device__ int   g_cnt1[64];          // qkv row-tiles: target 24
static __device__ int   g_cnt2h[64*HEADS];   // (attn row-tile, head): target 1

// ---------------------------------------------------------------------------
__device__ __forceinline__ unsigned f2tf(float x) {
    unsigned r;
    asm("cvt.rna.tf32.f32 %0, %1;" : "=r"(r) : "f"(x));
    return r;
}

__device__ __forceinline__ float fex2(float x) {   // 2^x, clamped below
    float r;
    x = fmaxf(x, -126.f);
    asm("ex2.approx.ftz.f32 %0, %1;" : "=f"(r) : "f"(x));
    return r;
}

__device__ __forceinline__ int permcol(int c) {
    int reg = c >> 10;
    if (reg == 1) return (c & ~7)  | ((c & 3) << 1) | ((c >> 2) & 1);
    if (reg == 2) return (c & ~15) | ((c & 7) << 1) | ((c >> 3) & 1);
    return c;
}

__device__ __forceinline__ void mma_tf32(float& c0, float& c1, float& c2, float& c3,
                                         unsigned a0, unsigned a1, unsigned a2, unsigned a3,
                                         unsigned b0, unsigned b1) {
    asm volatile(
        "mma.sync.aligned.m16n8k8.row.col.f32.tf32.tf32.f32 "
        "{%0,%1,%2,%3}, {%4,%5,%6,%7}, {%8,%9}, {%0,%1,%2,%3};\n"
        : "+f"(c0), "+f"(c1), "+f"(c2), "+f"(c3)
        : "r"(a0), "r"(a1), "r"(a2), "r"(a3), "r"(b0), "r"(b1));
}

#define CP_ASYNC16(dst, src) \
    asm volatile("cp.async.cg.shared.global [%0], [%1], 16;\n" :: "r"(dst), "l"(src))

// classic flag wait: producer did __threadfence()+atomicAdd (release);
// consumer polls volatile then __threadfence() (acquire).
__device__ __forceinline__ void waitcnt(const int* c, int target) {
    if (*(volatile const int*)c < target) {
        while (*(volatile const int*)c < target) __nanosleep(128);
    }
    __threadfence();
}

// ---------------------------------------------------------------------------
// prep: zero counters + wq cvt (blocks 0..3071) + wo cvt + ln
// ---------------------------------------------------------------------------
#define PREP_WQ_BLKS 3072
#define PREP_WO_BLKS 1024
#define PREP_BLKS    (PREP_WQ_BLKS + PREP_WO_BLKS + ROWS)

__global__ __launch_bounds__(256) void prep_kernel(const float* __restrict__ w_qkv,
                                                   const float* __restrict__ w_out,
                                                   const float* __restrict__ x,
                                                   const float* __restrict__ gamma,
                                                   const float* __restrict__ beta) {
    cudaTriggerProgrammaticLaunchCompletion();
    const int blk = blockIdx.x;
    const int t = threadIdx.x;

    if (blk == 0) {
        if (t < 64) g_cnt1[t] = 0;
        for (int i = t; i < 64 * HEADS; i += 256) g_cnt2h[i] = 0;
    }

    if (blk < PREP_WQ_BLKS + PREP_WO_BLKS) {
        const float* src = (blk < PREP_WQ_BLKS) ? w_qkv : w_out;
        float* dst       = (blk < PREP_WQ_BLKS) ? g_wq  : g_wo;
        int i = (blk < PREP_WQ_BLKS ? blk : blk - PREP_WQ_BLKS) * 256 + t;
        float4 v = ((const float4*)src)[i];
        uint4 o;
        o.x = f2tf(v.x); o.y = f2tf(v.y); o.z = f2tf(v.z); o.w = f2tf(v.w);
        ((uint4*)dst)[i] = o;
        return;
    }

    __shared__ float red[16];
    const int row = blk - (PREP_WQ_BLKS + PREP_WO_BLKS);
    const float* xr = x + (size_t)row * DIMN;
    float4 v = *(const float4*)(xr + t * 4);
    float s = v.x + v.y + v.z + v.w;
    float q = v.x*v.x + v.y*v.y + v.z*v.z + v.w*v.w;
    #pragma unroll
    for (int o = 16; o; o >>= 1) {
        s += __shfl_xor_sync(0xffffffffu, s, o);
        q += __shfl_xor_sync(0xffffffffu, q, o);
    }
    if ((t & 31) == 0) { red[t >> 5] = s; red[8 + (t >> 5)] = q; }
    __syncthreads();
    if (t < 32) {
        float ss = (t < 8) ? red[t] : 0.f;
        float qq = (t < 8) ? red[8 + t] : 0.f;
        #pragma unroll
        for (int o = 4; o; o >>= 1) {
            ss += __shfl_xor_sync(0xffffffffu, ss, o);
            qq += __shfl_xor_sync(0xffffffffu, qq, o);
        }
        if (t == 0) { red[0] = ss; red[1] = qq; }
    }
    __syncthreads();
    const float mean = red[0] * (1.f / DIMN);
    const float var  = red[1] * (1.f / DIMN) - mean * mean;
    const float inv  = rsqrtf(var + 1e-5f);
    float4 g = *(const float4*)(gamma + t * 4);
    float4 b = *(const float4*)(beta  + t * 4);
    uint4 o4;
    o4.x = f2tf((v.x - mean) * inv * g.x + b.x);
    o4.y = f2tf((v.y - mean) * inv * g.y + b.y);
    o4.z = f2tf((v.z - mean) * inv * g.z + b.z);
    o4.w = f2tf((v.w - mean) * inv * g.w + b.w);
    *(uint4*)(g_xn + (size_t)row * DIMN + t * 4) = o4;
}

// ---------------------------------------------------------------------------
// GEMM body (R13, proven) + optional per-head wait table for A chunks.
// hwait: if non-null, chunk kb requires hwait[kb>>1] >= 1 before loading.
// ---------------------------------------------------------------------------
#define ASTR 36
#define BSTR 136
#define ABUF (128*ASTR)
#define BBUF (32*BSTR)
#define STG  (ABUF+BBUF)

__device__ __forceinline__ void gemm_body(const float* __restrict__ A,
                                          const float* __restrict__ B,
                                          const float* __restrict__ bias,
                                          float* __restrict__ C,
                                          int N, int K, int mode,
                                          int bm, int bn, float* sm,
                                          const int* hwait) {
    const int tid = threadIdx.x;
    const int wid = tid >> 5, lane = tid & 31;
    const int g = lane >> 2, tg = lane & 3;
    const int wm = wid >> 1, wn = wid & 1;

    float c[2][8][4] = {};

    auto loadAB = [&](int buf, int k0) {
        float* As = sm + buf * STG;
        float* Bs = As + ABUF;
        unsigned abase = (unsigned)__cvta_generic_to_shared(As);
        unsigned bbase = (unsigned)__cvta_generic_to_shared(Bs);
        #pragma unroll
        for (int p = 0; p < 4; p++) {
            int idx = tid + p * 256;
            int ar = idx >> 3, ac = (idx & 7) * 4;
            CP_ASYNC16(abase + (ar * ASTR + ac) * 4, A + (size_t)(bm + ar) * K + k0 + ac);
            int br = idx >> 5, bc = (idx & 31) * 4;
            CP_ASYNC16(bbase + (br * BSTR + bc) * 4, B + (size_t)(k0 + br) * N + bn + bc);
        }
    };

    const int nk = K / 32;
    if (hwait) waitcnt(hwait + 0, 1);      // chunks 0,1 touch head 0
    loadAB(0, 0);
    asm volatile("cp.async.commit_group;\n");
    loadAB(1, 32);
    asm volatile("cp.async.commit_group;\n");

    int cur = 0, nxt = 2;
    for (int kb = 0; kb < nk; kb++) {
        if (kb + 1 < nk) {
            asm volatile("cp.async.wait_group 1;\n");
        } else {
            asm volatile("cp.async.wait_group 0;\n");
        }
        __syncthreads();
        if (kb + 2 < nk) {
            if (hwait && (((kb + 2) & 1) == 0))
                waitcnt(hwait + ((kb + 2) >> 1), 1);
            loadAB(nxt, (kb + 2) * 32);
            asm volatile("cp.async.commit_group;\n");
        }

        const float* Ab = sm + cur * STG;
        const float* Bb = Ab + ABUF;
        #pragma unroll
        for (int ks = 0; ks < 4; ks++) {
            const int kk = ks * 8;
            unsigned a[2][4], b[8][2];
            #pragma unroll
            for (int mt = 0; mt < 2; mt++) {
                int r0 = wm * 32 + mt * 16;
                a[mt][0] = __float_as_uint(Ab[(r0 + g)     * ASTR + kk + tg]);
                a[mt][1] = __float_as_uint(Ab[(r0 + g + 8) * ASTR + kk + tg]);
                a[mt][2] = __float_as_uint(Ab[(r0 + g)     * ASTR + kk + tg + 4]);
                a[mt][3] = __float_as_uint(Ab[(r0 + g + 8) * ASTR + kk + tg + 4]);
            }
            #pragma unroll
            for (int nt = 0; nt < 8; nt++) {
                int col = wn * 64 + nt * 8 + g;
                b[nt][0] = __float_as_uint(Bb[(kk + tg)     * BSTR + col]);
                b[nt][1] = __float_as_uint(Bb[(kk + tg + 4) * BSTR + col]);
            }
            #pragma unroll
            for (int mt = 0; mt < 2; mt++)
                #pragma unroll
                for (int nt = 0; nt < 8; nt++)
                    mma_tf32(c[mt][nt][0], c[mt][nt][1], c[mt][nt][2], c[mt][nt][3],
                             a[mt][0], a[mt][1], a[mt][2], a[mt][3],
                             b[nt][0], b[nt][1]);
        }
        cur = (cur == 2) ? 0 : cur + 1;
        nxt = (nxt == 2) ? 0 : nxt + 1;
    }

    #pragma unroll
    for (int mt = 0; mt < 2; mt++) {
        int r0 = bm + wm * 32 + mt * 16 + g;
        #pragma unroll
        for (int nt = 0; nt < 8; nt++) {
            int col = bn + wn * 64 + nt * 8 + 2 * tg;
            if (mode == 0) {
                float b0 = bias ? bias[col] : 0.f, b1 = bias ? bias[col + 1] : 0.f;
                *(float2*)(C + (size_t)r0 * N + col) =
                    make_float2(c[mt][nt][0] + b0, c[mt][nt][1] + b1);
                *(float2*)(C + (size_t)(r0 + 8) * N + col) =
                    make_float2(c[mt][nt][2] + b0, c[mt][nt][3] + b1);
            } else {
                int c0 = permcol(col), c1 = permcol(col + 1);
                C[(size_t)r0 * N + c0]       = __uint_as_float(f2tf(c[mt][nt][0]));
                C[(size_t)r0 * N + c1]       = __uint_as_float(f2tf(c[mt][nt][1]));
                C[(size_t)(r0 + 8) * N + c0] = __uint_as_float(f2tf(c[mt][nt][2]));
                C[(size_t)(r0 + 8) * N + c1] = __uint_as_float(f2tf(c[mt][nt][3]));
            }
        }
    }
}

// ---------------------------------------------------------------------------
// Flash body (R13, proven) with per-tile producer waits on g_cnt1.
// ---------------------------------------------------------------------------
#define FSK 72
#define FSV 72
#define FSP 68
#define KBUF (64*FSK)
#define VBUF (64*FSV)
#define FL_SMF (2*KBUF + 2*VBUF + 128*FSP)    /* 27136 floats = 108544 B */

__device__ __forceinline__ void flash_body(int qt, int b, int h, float* sm) {
    float* Ks = sm;
    float* Vs = sm + 2 * KBUF;
    float* Ps = sm + 2 * KBUF + 2 * VBUF;

    const int tid = threadIdx.x;
    const int wid = tid >> 5, lane = tid & 31;
    const int g = lane >> 2, tg = lane & 3;
    const int qr = wid * 16;
    const size_t base = (size_t)b * SEQ;
    const int qoff = h * DHEAD;
    const int koff = DIMN + h * DHEAD;
    const int voff = 2 * DIMN + h * DHEAD;
    const float* qkv = g_qkv;
    const int ct0 = b * 16;

    waitcnt(&g_cnt1[ct0 + qt], 24);
    #pragma unroll
    for (int p = 0; p < 8; p++) {
        int idx = tid + p * 256;
        int row = idx >> 4, c4 = (idx & 15) * 4;
        *(float4*)(Ps + row * FSP + c4) =
            *(const float4*)(qkv + (base + qt * 128 + row) * QKV_N + qoff + c4);
    }
    __syncthreads();
    unsigned qf[8][4];
    {
        const float QS = 0.125f * 1.4426950408889634f;
        const int r0 = (qr + g) * FSP, r1 = (qr + g + 8) * FSP;
        #pragma unroll
        for (int ks = 0; ks < 8; ks++) {
            int c = ks * 8 + tg;
            qf[ks][0] = f2tf(Ps[r0 + c]     * QS);
            qf[ks][1] = f2tf(Ps[r1 + c]     * QS);
            qf[ks][2] = f2tf(Ps[r0 + c + 4] * QS);
            qf[ks][3] = f2tf(Ps[r1 + c + 4] * QS);
        }
    }

    auto loadKV = [&](int buf, int kt) {
        unsigned kbase = (unsigned)__cvta_generic_to_shared(Ks + buf * KBUF);
        unsigned vbase = (unsigned)__cvta_generic_to_shared(Vs + buf * VBUF);
        #pragma unroll
        for (int p = 0; p < 4; p++) {
            int idx = tid + p * 256;
            int row = idx >> 4, c4 = (idx & 15) * 4;
            const float* rp = qkv + (base + kt * 64 + row) * QKV_N;
            CP_ASYNC16(kbase + (row * FSK + c4) * 4, rp + koff + c4);
            CP_ASYNC16(vbase + (row * FSV + c4) * 4, rp + voff + c4);
        }
    };

    int kvw = -1;
    auto wait_kv = [&](int j) {
        if (j > kvw) { waitcnt(&g_cnt1[ct0 + j], 24); kvw = j; }
    };

    float l[2] = {0.f, 0.f};
    float c[4][2][4] = {};

    const int NT = SEQ / 64;
    wait_kv(0);
    loadKV(0, 0);
    asm volatile("cp.async.commit_group;\n");

    for (int kt = 0; kt < NT; kt++) {
        asm volatile("cp.async.wait_group 0;\n");
        __syncthreads();
        if (kt + 1 < NT) {
            wait_kv((kt + 1) >> 1);
            loadKV((kt + 1) & 1, kt + 1);
            asm volatile("cp.async.commit_group;\n");
        }

        const float* Kb = Ks + (kt & 1) * KBUF;
        const float* Vb = Vs + (kt & 1) * VBUF;

        float sc[8][4] = {};
        #pragma unroll
        for (int ks = 0; ks < 8; ks++) {
            const int kk = ks * 8;
            #pragma unroll
            for (int nt = 0; nt < 8; nt++) {
                float2 bb = *(const float2*)&Kb[(nt * 8 + g) * FSK + kk + 2 * tg];
                mma_tf32(sc[nt][0], sc[nt][1], sc[nt][2], sc[nt][3],
                         qf[ks][0], qf[ks][1], qf[ks][2], qf[ks][3],
                         __float_as_uint(bb.x), __float_as_uint(bb.y));
            }
        }

        #pragma unroll
        for (int rh = 0; rh < 2; rh++) {
            float rs = 0.f;
            int prow = (qr + g + 8 * rh) * FSP;
            #pragma unroll
            for (int nt = 0; nt < 8; nt++) {
                float p0 = __uint_as_float(f2tf(fex2(sc[nt][2 * rh])));
                float p1 = __uint_as_float(f2tf(fex2(sc[nt][2 * rh + 1])));
                rs += p0 + p1;
                *(float2*)(Ps + prow + nt * 8 + 2 * tg) = make_float2(p0, p1);
            }
            rs += __shfl_xor_sync(0xffffffffu, rs, 1);
            rs += __shfl_xor_sync(0xffffffffu, rs, 2);
            l[rh] += rs;
        }
        __syncwarp();

        #pragma unroll
        for (int ks = 0; ks < 8; ks++) {
            const int kk = ks * 8;
            unsigned pb[2][2];
            #pragma unroll
            for (int nh = 0; nh < 2; nh++) {
                pb[nh][0] = __float_as_uint(Ps[(qr + nh * 8 + g) * FSP + kk + tg]);
                pb[nh][1] = __float_as_uint(Ps[(qr + nh * 8 + g) * FSP + kk + tg + 4]);
            }
            #pragma unroll
            for (int mt = 0; mt < 4; mt++) {
                float2 va0 = *(const float2*)&Vb[(kk + tg)     * FSV + mt * 16 + 2 * g];
                float2 va1 = *(const float2*)&Vb[(kk + tg + 4) * FSV + mt * 16 + 2 * g];
                #pragma unroll
                for (int nh = 0; nh < 2; nh++)
                    mma_tf32(c[mt][nh][0], c[mt][nh][1], c[mt][nh][2], c[mt][nh][3],
                             __float_as_uint(va0.x), __float_as_uint(va0.y),
                             __float_as_uint(va1.x), __float_as_uint(va1.y),
                             pb[nh][0], pb[nh][1]);
            }
        }
        __syncwarp();
    }

    float linv[2][2];
    #pragma unroll
    for (int nh = 0; nh < 2; nh++) {
        linv[nh][0] = 1.f / __shfl_sync(0xffffffffu, l[nh], 8 * tg);
        linv[nh][1] = 1.f / __shfl_sync(0xffffffffu, l[nh], 8 * tg + 4);
    }
    #pragma unroll
    for (int mt = 0; mt < 4; mt++) {
        #pragma unroll
        for (int nh = 0; nh < 2; nh++) {
            int q = qt * 128 + qr + nh * 8 + 2 * tg;
            int d0 = mt * 16 + g;
            size_t ro = (base + q) * (size_t)DIMN + h * DHEAD;
            g_attn[ro + d0]            = __uint_as_float(f2tf(c[mt][nh][0] * linv[nh][0]));
            g_attn[ro + DIMN + d0]     = __uint_as_float(f2tf(c[mt][nh][1] * linv[nh][1]));
            g_attn[ro + d0 + 8]        = __uint_as_float(f2tf(c[mt][nh][2] * linv[nh][0]));
            g_attn[ro + DIMN + d0 + 8] = __uint_as_float(f2tf(c[mt][nh][3] * linv[nh][1]));
        }
    }
}

// ---------------------------------------------------------------------------
// Fused kernel, R13 dispatch order:
//   gemm1 (0..1535, bm-major) | flash (1536..2559) | gemm2 (2560..3071)
// gemm2 uses per-(rowtile,head) waits so its K-stream overlaps flash tail.
// ---------------------------------------------------------------------------
#define G1 1536
#define G2 1024
#define G3 512
#define FUSED_SMEM 108544

__global__ __launch_bounds__(256, 2) void fused_kernel(const float* __restrict__ b_out,
                                                       float* __restrict__ out) {
    extern __shared__ float sm[];
    cudaGridDependencySynchronize();       // prep done (xn, weights, counters=0)
    cudaTriggerProgrammaticLaunchCompletion();

    const int bid = blockIdx.x;
    const int tid = threadIdx.x;

    if (bid < G1) {
        // gemm1: bm-major so qkv row-tiles complete in order
        const int bm = (bid / 24) * 128, bn = (bid % 24) * 128;
        gemm_body(g_xn, g_wq, nullptr, g_qkv, QKV_N, DIMN, 1, bm, bn, sm, nullptr);
        __syncthreads();
        if (tid == 0) { __threadfence(); atomicAdd(&g_cnt1[bm >> 7], 1); }
    } else if (bid < G1 + G2) {
        // flash: batch-major, qt next, head fastest
        const int f = bid - G1;
        const int b = f >> 8, r = f & 255, qt = r >> 4, h = r & 15;
        flash_body(qt, b, h, sm);
        __syncthreads();
        if (tid == 0) {
            __threadfence();
            atomicAdd(&g_cnt2h[(b * 16 + qt) * HEADS + h], 1);
        }
    } else {
        // gemm2: bm-major; per-head incremental waits inside gemm_body
        const int z = bid - G1 - G2;
        const int bm = (z >> 3) * 128, bn = (z & 7) * 128;
        gemm_body(g_attn, g_wo, b_out, out, DIMN, DIMN, 0, bm, bn, sm,
                  g_cnt2h + (bm >> 7) * HEADS);
    }
}

// ---------------------------------------------------------------------------
extern "C" void kernel_launch(void* const* d_in, const int* in_sizes, int n_in,
                              void* d_out, int out_size)
{
    const float* x      = (const float*)d_in[0];
    const float* gamma  = (const float*)d_in[1];
    const float* beta   = (const float*)d_in[2];
    const float* w_qkv  = (const float*)d_in[3];
    const float* w_out  = (const float*)d_in[4];
    const float* b_out  = (const float*)d_in[5];
    float* out = (float*)d_out;

    cudaFuncSetAttribute(fused_kernel, cudaFuncAttributeMaxDynamicSharedMemorySize,
                         FUSED_SMEM);

    cudaLaunchAttribute pdl[1];
    pdl[0].id = cudaLaunchAttributeProgrammaticStreamSerialization;
    pdl[0].val.programmaticStreamSerializationAllowed = 1;

    prep_kernel<<<PREP_BLKS, 256>>>(w_qkv, w_out, x, gamma, beta);

    cudaLaunchConfig_t cfg = {};
    cfg.gridDim = dim3(G1 + G2 + G3);
    cfg.blockDim = dim3(256);
    cfg.dynamicSmemBytes = FUSED_SMEM;
    cfg.stream = 0;
    cfg.attrs = pdl;
    cfg.numAttrs = 1;
    cudaLaunchKernelEx(&cfg, fused_kernel, b_out, out);
}

// round 16
// speedup vs baseline: 1.5539x; 1.4968x over previous
#include <cuda_runtime.h>
#include <cuda_fp16.h>
#include <math.h>

#define BATCH 4
#define SEQ   2048
#define DIMN  1024
#define HEADS 16
#define DHEAD 64
#define ROWS  (BATCH*SEQ)      /* 8192 */
#define QKV_N (3*DIMN)         /* 3072 */

// Scratch (allocation-free rule: __device__ globals) — all fp16 now
static __device__ __half g_xn[(size_t)ROWS*DIMN];
static __device__ __half g_qk[(size_t)ROWS*2048];        // [row][ Q(1024) | K(1024) ]
static __device__ __half g_v[(size_t)(ROWS/2)*2048];     // V pair-packed: [row>>1][2*d + (row&1)]
static __device__ __half g_attn[(size_t)ROWS*DIMN];
static __device__ __half g_wq2[(size_t)DIMN*QKV_N];      // w_qkv k-pair-interleaved: [(k>>1)][2n+(k&1)]
static __device__ __half g_wo2[(size_t)DIMN*DIMN];       // w_out  k-pair-interleaved
// progress counters
static __device__ int g_cnt1[64];   // qkv row-tiles: target 24
static __device__ int g_cnt2[64];   // attn row-tiles: target 16

// ---------------------------------------------------------------------------
__device__ __forceinline__ unsigned pack_h2(float x, float y) {
    __half2 h = __floats2half2_rn(x, y);
    return *(unsigned*)&h;
}
__device__ __forceinline__ float2 up_h2(unsigned v) {
    __half2 h = *(__half2*)&v;
    return __half22float2(h);
}
__device__ __forceinline__ float fex2(float x) {   // 2^x, clamped below
    float r;
    x = fmaxf(x, -126.f);
    asm("ex2.approx.ftz.f32 %0, %1;" : "=f"(r) : "f"(x));
    return r;
}

__device__ __forceinline__ void mma_f16(float& c0, float& c1, float& c2, float& c3,
                                        unsigned a0, unsigned a1, unsigned a2, unsigned a3,
                                        unsigned b0, unsigned b1) {
    asm volatile(
        "mma.sync.aligned.m16n8k16.row.col.f32.f16.f16.f32 "
        "{%0,%1,%2,%3}, {%4,%5,%6,%7}, {%8,%9}, {%0,%1,%2,%3};\n"
        : "+f"(c0), "+f"(c1), "+f"(c2), "+f"(c3)
        : "r"(a0), "r"(a1), "r"(a2), "r"(a3), "r"(b0), "r"(b1));
}

#define CP_ASYNC16(dst, src) \
    asm volatile("cp.async.cg.shared.global [%0], [%1], 16;\n" :: "r"(dst), "l"(src))

__device__ __forceinline__ void waitcnt(const int* c, int target) {
    if (*(volatile const int*)c < target) {
        while (*(volatile const int*)c < target) __nanosleep(128);
    }
    __threadfence();
}

// ---------------------------------------------------------------------------
// prep: zero counters + weight repack->fp16 (k-pair-interleave) + LN->fp16
// ---------------------------------------------------------------------------
#define PREP_WQ_BLKS 3072
#define PREP_WO_BLKS 1024
#define PREP_BLKS    (PREP_WQ_BLKS + PREP_WO_BLKS + ROWS)

__global__ __launch_bounds__(256) void prep_kernel(const float* __restrict__ w_qkv,
                                                   const float* __restrict__ w_out,
                                                   const float* __restrict__ x,
                                                   const float* __restrict__ gamma,
                                                   const float* __restrict__ beta) {
    cudaTriggerProgrammaticLaunchCompletion();
    const int blk = blockIdx.x;
    const int t = threadIdx.x;

    if (blk == 0 && t < 64) { g_cnt1[t] = 0; g_cnt2[t] = 0; }

    if (blk < PREP_WQ_BLKS) {                 // w_qkv: K=1024 x N=3072
        int i0 = blk * 1024 + t * 4;
        int k = i0 / QKV_N, n = i0 - k * QKV_N;
        float4 v = *(const float4*)(w_qkv + i0);
        __half* dst = g_wq2 + (size_t)(k >> 1) * (2 * QKV_N) + (k & 1) + 2 * n;
        dst[0] = __float2half_rn(v.x); dst[2] = __float2half_rn(v.y);
        dst[4] = __float2half_rn(v.z); dst[6] = __float2half_rn(v.w);
        return;
    }
    if (blk < PREP_WQ_BLKS + PREP_WO_BLKS) {  // w_out: K=1024 x N=1024
        int blk2 = blk - PREP_WQ_BLKS;
        int k = blk2, n = t * 4;
        float4 v = *(const float4*)(w_out + (size_t)k * DIMN + n);
        __half* dst = g_wo2 + (size_t)(k >> 1) * (2 * DIMN) + (k & 1) + 2 * n;
        dst[0] = __float2half_rn(v.x); dst[2] = __float2half_rn(v.y);
        dst[4] = __float2half_rn(v.z); dst[6] = __float2half_rn(v.w);
        return;
    }

    // LayerNorm row -> fp16
    __shared__ float red[16];
    const int row = blk - (PREP_WQ_BLKS + PREP_WO_BLKS);
    const float* xr = x + (size_t)row * DIMN;
    float4 v = *(const float4*)(xr + t * 4);
    float s = v.x + v.y + v.z + v.w;
    float q = v.x*v.x + v.y*v.y + v.z*v.z + v.w*v.w;
    #pragma unroll
    for (int o = 16; o; o >>= 1) {
        s += __shfl_xor_sync(0xffffffffu, s, o);
        q += __shfl_xor_sync(0xffffffffu, q, o);
    }
    if ((t & 31) == 0) { red[t >> 5] = s; red[8 + (t >> 5)] = q; }
    __syncthreads();
    if (t < 32) {
        float ss = (t < 8) ? red[t] : 0.f;
        float qq = (t < 8) ? red[8 + t] : 0.f;
        #pragma unroll
        for (int o = 4; o; o >>= 1) {
            ss += __shfl_xor_sync(0xffffffffu, ss, o);
            qq += __shfl_xor_sync(0xffffffffu, qq, o);
        }
        if (t == 0) { red[0] = ss; red[1] = qq; }
    }
    __syncthreads();
    const float mean = red[0] * (1.f / DIMN);
    const float var  = red[1] * (1.f / DIMN) - mean * mean;
    const float inv  = rsqrtf(var + 1e-5f);
    float4 gg = *(const float4*)(gamma + t * 4);
    float4 bb = *(const float4*)(beta  + t * 4);
    uint2 o2;
    o2.x = pack_h2((v.x - mean) * inv * gg.x + bb.x, (v.y - mean) * inv * gg.y + bb.y);
    o2.y = pack_h2((v.z - mean) * inv * gg.z + bb.z, (v.w - mean) * inv * gg.w + bb.w);
    *(uint2*)&g_xn[(size_t)row * DIMN + t * 4] = o2;
}

// ---------------------------------------------------------------------------
// fp16 GEMM body: A[m][k] half, B2 k-pair-interleaved [(k>>1)][2n+(k&1)].
// 128x128 tile, BK=32, 3-stage cp.async, one barrier per chunk.
// mode 0: fp32 out + bias. mode 1: half out split into g_qk / g_v(pair-packed).
// smem words/stage: A 128x20 (=2560) | B 16x132 (=2112); 3 stages = 14016 words.
// ---------------------------------------------------------------------------
#define GA_W 2560
#define GSTG_W 4672
#define GEMM_SMEM_W (3*GSTG_W)    /* 14016 words = 56064 B */

__device__ __forceinline__ void gemm_body(const __half* __restrict__ A,
                                          const __half* __restrict__ B2,
                                          const float* __restrict__ bias,
                                          void* __restrict__ Cv,
                                          int N, int K, int mode,
                                          int bm, int bn, unsigned* sm) {
    const int tid = threadIdx.x;
    const int wid = tid >> 5, lane = tid & 31;
    const int g = lane >> 2, tg = lane & 3;
    const int wm = wid >> 1, wn = wid & 1;
    const unsigned smb = (unsigned)__cvta_generic_to_shared(sm);

    float c[2][8][4] = {};

    auto loadAB = [&](int buf, int k0) {
        const unsigned aw = buf * GSTG_W, bw = aw + GA_W;
        #pragma unroll
        for (int p = 0; p < 2; p++) {
            int idx = tid + p * 256;
            int ar = idx >> 2, seg = idx & 3;
            CP_ASYNC16(smb + (aw + ar * 20 + seg * 4) * 4,
                       A + (size_t)(bm + ar) * K + k0 + seg * 8);
        }
        #pragma unroll
        for (int p = 0; p < 2; p++) {
            int idx = tid + p * 256;
            int br = idx >> 5, seg = idx & 31;
            CP_ASYNC16(smb + (bw + br * 132 + seg * 4) * 4,
                       B2 + (size_t)((k0 >> 1) + br) * (2 * N) + 2 * bn + seg * 8);
        }
        asm volatile("cp.async.commit_group;\n");
    };

    const int nk = K / 32;
    loadAB(0, 0);
    loadAB(1, 32);

    int cur = 0, nxt = 2;
    for (int kb = 0; kb < nk; kb++) {
        if (kb + 1 < nk) {
            asm volatile("cp.async.wait_group 1;\n");
        } else {
            asm volatile("cp.async.wait_group 0;\n");
        }
        __syncthreads();
        if (kb + 2 < nk) loadAB(nxt, (kb + 2) * 32);

        const unsigned* Ab = sm + cur * GSTG_W;
        const unsigned* Bb = Ab + GA_W;
        #pragma unroll
        for (int ks = 0; ks < 2; ks++) {
            unsigned a[2][4], b[8][2];
            #pragma unroll
            for (int mt = 0; mt < 2; mt++) {
                int r0 = wm * 32 + mt * 16;
                a[mt][0] = Ab[(r0 + g)     * 20 + 8 * ks + tg];
                a[mt][1] = Ab[(r0 + g + 8) * 20 + 8 * ks + tg];
                a[mt][2] = Ab[(r0 + g)     * 20 + 8 * ks + tg + 4];
                a[mt][3] = Ab[(r0 + g + 8) * 20 + 8 * ks + tg + 4];
            }
            #pragma unroll
            for (int nt = 0; nt < 8; nt++) {
                int col = wn * 64 + nt * 8 + g;
                b[nt][0] = Bb[(8 * ks + tg)     * 132 + col];
                b[nt][1] = Bb[(8 * ks + tg + 4) * 132 + col];
            }
            #pragma unroll
            for (int mt = 0; mt < 2; mt++)
                #pragma unroll
                for (int nt = 0; nt < 8; nt++)
                    mma_f16(c[mt][nt][0], c[mt][nt][1], c[mt][nt][2], c[mt][nt][3],
                            a[mt][0], a[mt][1], a[mt][2], a[mt][3],
                            b[nt][0], b[nt][1]);
        }
        cur = (cur == 2) ? 0 : cur + 1;
        nxt = (nxt == 2) ? 0 : nxt + 1;
    }

    #pragma unroll
    for (int mt = 0; mt < 2; mt++) {
        int r0 = bm + wm * 32 + mt * 16 + g;
        #pragma unroll
        for (int nt = 0; nt < 8; nt++) {
            int col = bn + wn * 64 + nt * 8 + 2 * tg;
            float v00 = c[mt][nt][0], v01 = c[mt][nt][1];
            float v10 = c[mt][nt][2], v11 = c[mt][nt][3];
            if (mode == 0) {
                float* C = (float*)Cv;
                float b0 = bias ? bias[col] : 0.f, b1 = bias ? bias[col + 1] : 0.f;
                *(float2*)(C + (size_t)r0 * N + col)       = make_float2(v00 + b0, v01 + b1);
                *(float2*)(C + (size_t)(r0 + 8) * N + col) = make_float2(v10 + b0, v11 + b1);
            } else if (col < 2048) {   // Q or K region -> g_qk, half2
                *(unsigned*)&g_qk[(size_t)r0 * 2048 + col]       = pack_h2(v00, v01);
                *(unsigned*)&g_qk[(size_t)(r0 + 8) * 2048 + col] = pack_h2(v10, v11);
            } else {                   // V region -> g_v pair-packed over rows
                int d = col - 2048;
                size_t vb0 = (size_t)(r0 >> 1) * 2048 + 2 * d + (r0 & 1);
                g_v[vb0]     = __float2half_rn(v00);
                g_v[vb0 + 2] = __float2half_rn(v01);
                size_t vb1 = (size_t)((r0 + 8) >> 1) * 2048 + 2 * d + ((r0 + 8) & 1);
                g_v[vb1]     = __float2half_rn(v10);
                g_v[vb1 + 2] = __float2half_rn(v11);
            }
        }
    }
}

// ---------------------------------------------------------------------------
// fp16 flash body: 128 q-rows/CTA, 8 warps x 16 rows, 64-key tiles,
// online-max softmax (fp16 P range safety), single barrier per tile.
// smem words: Ks 2x64x36 (4608) | Vs 2x32x68 (4352) | Ps/Q 128x36 (4608)
// ---------------------------------------------------------------------------
#define FK_W 2304
#define FV_W 2176
#define FVS_BASE 4608
#define FPS_BASE 8960
#define FLASH_SMEM_W 13568        /* 54272 B */

__device__ __forceinline__ void flash_body(int qt, int b, int h, unsigned* sm) {
    const int tid = threadIdx.x;
    const int wid = tid >> 5, lane = tid & 31;
    const int g = lane >> 2, tg = lane & 3;
    const int qr = wid * 16;
    const size_t base = (size_t)b * SEQ;
    const size_t bv = (size_t)b * (SEQ / 2);
    const int ct0 = b * 16;
    const unsigned smb = (unsigned)__cvta_generic_to_shared(sm);
    unsigned* Ks = sm;
    unsigned* Vs = sm + FVS_BASE;
    unsigned* Ps = sm + FPS_BASE;   // doubles as Q stage

    // ---- Q stage ----
    waitcnt(&g_cnt1[ct0 + qt], 24);
    #pragma unroll
    for (int p = 0; p < 4; p++) {
        int idx = tid + p * 256;
        int row = idx >> 3, seg = idx & 7;
        CP_ASYNC16(smb + (FPS_BASE + row * 36 + seg * 4) * 4,
                   g_qk + (base + qt * 128 + row) * 2048 + h * DHEAD + seg * 8);
    }
    asm volatile("cp.async.commit_group;\n");
    asm volatile("cp.async.wait_group 0;\n");
    __syncthreads();

    unsigned qf[4][4];
    {
        const float QS = 0.125f * 1.4426950408889634f;
        const int r0 = (qr + g) * 36, r1 = (qr + g + 8) * 36;
        #pragma unroll
        for (int ks = 0; ks < 4; ks++) {
            #pragma unroll
            for (int j = 0; j < 4; j++) {
                int idx = ((j & 1) ? r1 : r0) + 8 * ks + tg + ((j >> 1) ? 4 : 0);
                float2 f = up_h2(Ps[idx]);
                qf[ks][j] = pack_h2(f.x * QS, f.y * QS);
            }
        }
    }

    auto loadKV = [&](int buf, int kt) {
        #pragma unroll
        for (int p = 0; p < 2; p++) {
            int idx = tid + p * 256;
            int row = idx >> 3, seg = idx & 7;
            CP_ASYNC16(smb + (buf * FK_W + row * 36 + seg * 4) * 4,
                       g_qk + (base + kt * 64 + row) * 2048 + 1024 + h * DHEAD + seg * 8);
        }
        #pragma unroll
        for (int p = 0; p < 2; p++) {
            int idx = tid + p * 256;
            int rp = idx >> 4, seg = idx & 15;
            CP_ASYNC16(smb + (FVS_BASE + buf * FV_W + rp * 68 + seg * 4) * 4,
                       g_v + (bv + kt * 32 + rp) * 2048 + h * 128 + seg * 8);
        }
        asm volatile("cp.async.commit_group;\n");
    };

    int kvw = -1;
    auto wait_kv = [&](int j) {
        if (j > kvw) { waitcnt(&g_cnt1[ct0 + j], 24); kvw = j; }
    };

    const float NEG = -3.0e38f;
    float m[2] = {NEG, NEG}, l[2] = {0.f, 0.f};
    float c[8][4] = {};

    const int NT = SEQ / 64;
    wait_kv(0);
    loadKV(0, 0);

    for (int kt = 0; kt < NT; kt++) {
        asm volatile("cp.async.wait_group 0;\n");
        __syncthreads();
        if (kt + 1 < NT) {
            wait_kv((kt + 1) >> 1);
            loadKV((kt + 1) & 1, kt + 1);
        }

        const unsigned* Kb = Ks + (kt & 1) * FK_W;
        const unsigned* Vb = Vs + (kt & 1) * FV_W;

        // ---- S = Q @ K^T (log2 domain) ----
        float sc[8][4] = {};
        #pragma unroll
        for (int ks = 0; ks < 4; ks++) {
            #pragma unroll
            for (int nt = 0; nt < 8; nt++) {
                unsigned b0 = Kb[(nt * 8 + g) * 36 + 8 * ks + tg];
                unsigned b1 = Kb[(nt * 8 + g) * 36 + 8 * ks + tg + 4];
                mma_f16(sc[nt][0], sc[nt][1], sc[nt][2], sc[nt][3],
                        qf[ks][0], qf[ks][1], qf[ks][2], qf[ks][3], b0, b1);
            }
        }

        // ---- online softmax with running max (fp16 P range safety) ----
        #pragma unroll
        for (int rh = 0; rh < 2; rh++) {
            float mt = NEG;
            #pragma unroll
            for (int nt = 0; nt < 8; nt++)
                mt = fmaxf(mt, fmaxf(sc[nt][2 * rh], sc[nt][2 * rh + 1]));
            mt = fmaxf(mt, __shfl_xor_sync(0xffffffffu, mt, 1));
            mt = fmaxf(mt, __shfl_xor_sync(0xffffffffu, mt, 2));
            float mn = fmaxf(m[rh], mt);
            float fs = fex2(m[rh] - mn);
            float rs = 0.f;
            int prow = (qr + g + 8 * rh) * 36;
            #pragma unroll
            for (int nt = 0; nt < 8; nt++) {
                unsigned ph = pack_h2(fex2(sc[nt][2 * rh] - mn),
                                      fex2(sc[nt][2 * rh + 1] - mn));
                float2 pf = up_h2(ph);
                rs += pf.x + pf.y;
                Ps[prow + nt * 4 + tg] = ph;
            }
            rs += __shfl_xor_sync(0xffffffffu, rs, 1);
            rs += __shfl_xor_sync(0xffffffffu, rs, 2);
            l[rh] = l[rh] * fs + rs;
            m[rh] = mn;
            #pragma unroll
            for (int nt = 0; nt < 8; nt++) {
                c[nt][2 * rh]     *= fs;
                c[nt][2 * rh + 1] *= fs;
            }
        }
        __syncwarp();

        // ---- O += P @ V ----
        #pragma unroll
        for (int ks = 0; ks < 4; ks++) {
            unsigned a0 = Ps[(qr + g)     * 36 + 8 * ks + tg];
            unsigned a1 = Ps[(qr + g + 8) * 36 + 8 * ks + tg];
            unsigned a2 = Ps[(qr + g)     * 36 + 8 * ks + tg + 4];
            unsigned a3 = Ps[(qr + g + 8) * 36 + 8 * ks + tg + 4];
            #pragma unroll
            for (int nt = 0; nt < 8; nt++) {
                unsigned b0 = Vb[(8 * ks + tg)     * 68 + nt * 8 + g];
                unsigned b1 = Vb[(8 * ks + tg + 4) * 68 + nt * 8 + g];
                mma_f16(c[nt][0], c[nt][1], c[nt][2], c[nt][3],
                        a0, a1, a2, a3, b0, b1);
            }
        }
        __syncwarp();
    }

    // ---- epilogue: normalize, store fp16 ----
    const float i0 = 1.f / l[0], i1 = 1.f / l[1];
    size_t r0 = (base + qt * 128 + qr + g) * (size_t)DIMN + h * DHEAD;
    size_t r1 = r0 + 8 * (size_t)DIMN;
    #pragma unroll
    for (int nt = 0; nt < 8; nt++) {
        int col = nt * 8 + 2 * tg;
        *(unsigned*)&g_attn[r0 + col] = pack_h2(c[nt][0] * i0, c[nt][1] * i0);
        *(unsigned*)&g_attn[r1 + col] = pack_h2(c[nt][2] * i1, c[nt][3] * i1);
    }
}

// ---------------------------------------------------------------------------
// Fused kernel (R13 dispatch): gemm1 | flash | gemm2 with progress counters.
// ---------------------------------------------------------------------------
#define G1 1536
#define G2 1024
#define G3 512
#define FUSED_SMEM 56064

__global__ __launch_bounds__(256, 2) void fused_kernel(const float* __restrict__ b_out,
                                                       float* __restrict__ out) {
    extern __shared__ unsigned smw[];
    cudaGridDependencySynchronize();
    cudaTriggerProgrammaticLaunchCompletion();

    const int bid = blockIdx.x;
    const int tid = threadIdx.x;

    if (bid < G1) {
        const int bm = (bid / 24) * 128, bn = (bid % 24) * 128;
        gemm_body(g_xn, g_wq2, nullptr, nullptr, QKV_N, DIMN, 1, bm, bn, smw);
        __syncthreads();
        if (tid == 0) { __threadfence(); atomicAdd(&g_cnt1[bm >> 7], 1); }
    } else if (bid < G1 + G2) {
        const int f = bid - G1;
        const int b = f >> 8, r = f & 255, qt = r >> 4, h = r & 15;
        flash_body(qt, b, h, smw);
        __syncthreads();
        if (tid == 0) { __threadfence(); atomicAdd(&g_cnt2[b * 16 + qt], 1); }
    } else {
        const int z = bid - G1 - G2;
        const int bm = (z >> 3) * 128, bn = (z & 7) * 128;
        waitcnt(&g_cnt2[bm >> 7], 16);
        gemm_body(g_attn, g_wo2, b_out, out, DIMN, DIMN, 0, bm, bn, smw);
    }
}

// ---------------------------------------------------------------------------
extern "C" void kernel_launch(void* const* d_in, const int* in_sizes, int n_in,
                              void* d_out, int out_size)
{
    const float* x      = (const float*)d_in[0];
    const float* gamma  = (const float*)d_in[1];
    const float* beta   = (const float*)d_in[2];
    const float* w_qkv  = (const float*)d_in[3];
    const float* w_out  = (const float*)d_in[4];
    const float* b_out  = (const float*)d_in[5];
    float* out = (float*)d_out;

    cudaFuncSetAttribute(fused_kernel, cudaFuncAttributeMaxDynamicSharedMemorySize,
                         FUSED_SMEM);

    cudaLaunchAttribute pdl[1];
    pdl[0].id = cudaLaunchAttributeProgrammaticStreamSerialization;
    pdl[0].val.programmaticStreamSerializationAllowed = 1;

    prep_kernel<<<PREP_BLKS, 256>>>(w_qkv, w_out, x, gamma, beta);

    cudaLaunchConfig_t cfg = {};
    cfg.gridDim = dim3(G1 + G2 + G3);
    cfg.blockDim = dim3(256);
    cfg.dynamicSmemBytes = FUSED_SMEM;
    cfg.stream = 0;
    cfg.attrs = pdl;
    cfg.numAttrs = 1;
    cudaLaunchKernelEx(&cfg, fused_kernel, b_out, out);
}

// round 17
// speedup vs baseline: 1.8567x; 1.1948x over previous
#include <cuda_runtime.h>
#include <cuda_fp16.h>
#include <math.h>

#define BATCH 4
#define SEQ   2048
#define DIMN  1024
#define HEADS 16
#define DHEAD 64
#define ROWS  (BATCH*SEQ)      /* 8192 */
#define QKV_N (3*DIMN)         /* 3072 */

// Scratch (allocation-free rule: __device__ globals) — fp16
static __device__ __half g_xn[(size_t)ROWS*DIMN];
static __device__ __half g_qk[(size_t)ROWS*2048];        // [row][ Q(1024) | K(1024) ]
static __device__ __half g_v[(size_t)(ROWS/2)*2048];     // V pair-packed: [row>>1][2*d + (row&1)]
static __device__ __half g_attn[(size_t)ROWS*DIMN];
static __device__ __half g_wq2[(size_t)DIMN*QKV_N];      // w_qkv k-pair-interleaved
static __device__ __half g_wo2[(size_t)DIMN*DIMN];       // w_out  k-pair-interleaved
// progress counters
static __device__ int g_cnt1[64];   // qkv row-tiles: target 24
static __device__ int g_cnt2[64];   // attn row-tiles: target 16

// ---------------------------------------------------------------------------
__device__ __forceinline__ unsigned pack_h2(float x, float y) {
    __half2 h = __floats2half2_rn(x, y);
    return *(unsigned*)&h;
}
__device__ __forceinline__ float2 up_h2(unsigned v) {
    __half2 h = *(__half2*)&v;
    return __half22float2(h);
}
__device__ __forceinline__ float fex2(float x) {
    float r;
    x = fmaxf(x, -126.f);
    asm("ex2.approx.ftz.f32 %0, %1;" : "=f"(r) : "f"(x));
    return r;
}

__device__ __forceinline__ void mma_f16(float& c0, float& c1, float& c2, float& c3,
                                        unsigned a0, unsigned a1, unsigned a2, unsigned a3,
                                        unsigned b0, unsigned b1) {
    asm volatile(
        "mma.sync.aligned.m16n8k16.row.col.f32.f16.f16.f32 "
        "{%0,%1,%2,%3}, {%4,%5,%6,%7}, {%8,%9}, {%0,%1,%2,%3};\n"
        : "+f"(c0), "+f"(c1), "+f"(c2), "+f"(c3)
        : "r"(a0), "r"(a1), "r"(a2), "r"(a3), "r"(b0), "r"(b1));
}

#define CP_ASYNC16(dst, src) \
    asm volatile("cp.async.cg.shared.global [%0], [%1], 16;\n" :: "r"(dst), "l"(src))

__device__ __forceinline__ void waitcnt(const int* c, int target) {
    if (*(volatile const int*)c < target) {
        while (*(volatile const int*)c < target) __nanosleep(128);
    }
    __threadfence();
}

// ---------------------------------------------------------------------------
// prep (unchanged from R16): zero counters + weight repack->fp16 + LN->fp16
// ---------------------------------------------------------------------------
#define PREP_WQ_BLKS 3072
#define PREP_WO_BLKS 1024
#define PREP_BLKS    (PREP_WQ_BLKS + PREP_WO_BLKS + ROWS)

__global__ __launch_bounds__(256) void prep_kernel(const float* __restrict__ w_qkv,
                                                   const float* __restrict__ w_out,
                                                   const float* __restrict__ x,
                                                   const float* __restrict__ gamma,
                                                   const float* __restrict__ beta) {
    cudaTriggerProgrammaticLaunchCompletion();
    const int blk = blockIdx.x;
    const int t = threadIdx.x;

    if (blk == 0 && t < 64) { g_cnt1[t] = 0; g_cnt2[t] = 0; }

    if (blk < PREP_WQ_BLKS) {
        int i0 = blk * 1024 + t * 4;
        int k = i0 / QKV_N, n = i0 - k * QKV_N;
        float4 v = *(const float4*)(w_qkv + i0);
        __half* dst = g_wq2 + (size_t)(k >> 1) * (2 * QKV_N) + (k & 1) + 2 * n;
        dst[0] = __float2half_rn(v.x); dst[2] = __float2half_rn(v.y);
        dst[4] = __float2half_rn(v.z); dst[6] = __float2half_rn(v.w);
        return;
    }
    if (blk < PREP_WQ_BLKS + PREP_WO_BLKS) {
        int blk2 = blk - PREP_WQ_BLKS;
        int k = blk2, n = t * 4;
        float4 v = *(const float4*)(w_out + (size_t)k * DIMN + n);
        __half* dst = g_wo2 + (size_t)(k >> 1) * (2 * DIMN) + (k & 1) + 2 * n;
        dst[0] = __float2half_rn(v.x); dst[2] = __float2half_rn(v.y);
        dst[4] = __float2half_rn(v.z); dst[6] = __float2half_rn(v.w);
        return;
    }

    __shared__ float red[16];
    const int row = blk - (PREP_WQ_BLKS + PREP_WO_BLKS);
    const float* xr = x + (size_t)row * DIMN;
    float4 v = *(const float4*)(xr + t * 4);
    float s = v.x + v.y + v.z + v.w;
    float q = v.x*v.x + v.y*v.y + v.z*v.z + v.w*v.w;
    #pragma unroll
    for (int o = 16; o; o >>= 1) {
        s += __shfl_xor_sync(0xffffffffu, s, o);
        q += __shfl_xor_sync(0xffffffffu, q, o);
    }
    if ((t & 31) == 0) { red[t >> 5] = s; red[8 + (t >> 5)] = q; }
    __syncthreads();
    if (t < 32) {
        float ss = (t < 8) ? red[t] : 0.f;
        float qq = (t < 8) ? red[8 + t] : 0.f;
        #pragma unroll
        for (int o = 4; o; o >>= 1) {
            ss += __shfl_xor_sync(0xffffffffu, ss, o);
            qq += __shfl_xor_sync(0xffffffffu, qq, o);
        }
        if (t == 0) { red[0] = ss; red[1] = qq; }
    }
    __syncthreads();
    const float mean = red[0] * (1.f / DIMN);
    const float var  = red[1] * (1.f / DIMN) - mean * mean;
    const float inv  = rsqrtf(var + 1e-5f);
    float4 gg = *(const float4*)(gamma + t * 4);
    float4 bb = *(const float4*)(beta  + t * 4);
    uint2 o2;
    o2.x = pack_h2((v.x - mean) * inv * gg.x + bb.x, (v.y - mean) * inv * gg.y + bb.y);
    o2.y = pack_h2((v.z - mean) * inv * gg.z + bb.z, (v.w - mean) * inv * gg.w + bb.w);
    *(uint2*)&g_xn[(size_t)row * DIMN + t * 4] = o2;
}

// ---------------------------------------------------------------------------
// fp16 GEMM body — 128 threads, 4 warps of 64x64 (2wm x 2wn), BK=32,
// 3-stage cp.async. B smem stride 136 words (bank-clean 8tg+g).
// ---------------------------------------------------------------------------
#define GA_W 2560                  /* A: 128 rows x 20 words */
#define GB_W 2176                  /* B: 16 rows x 136 words */
#define GSTG_W (GA_W + GB_W)       /* 4736 */
#define GEMM_SMEM_W (3*GSTG_W)     /* 14208 words = 56832 B */

__device__ __forceinline__ void gemm_body(const __half* __restrict__ A,
                                          const __half* __restrict__ B2,
                                          const float* __restrict__ bias,
                                          void* __restrict__ Cv,
                                          int N, int K, int mode,
                                          int bm, int bn, unsigned* sm) {
    const int tid = threadIdx.x;
    const int wid = tid >> 5, lane = tid & 31;
    const int g = lane >> 2, tg = lane & 3;
    const int wm = wid >> 1, wn = wid & 1;
    const unsigned smb = (unsigned)__cvta_generic_to_shared(sm);

    float c[4][8][4] = {};

    auto loadAB = [&](int buf, int k0) {
        const unsigned aw = buf * GSTG_W, bw = aw + GA_W;
        #pragma unroll
        for (int p = 0; p < 4; p++) {
            int idx = tid + p * 128;
            int ar = idx >> 2, seg = idx & 3;
            CP_ASYNC16(smb + (aw + ar * 20 + seg * 4) * 4,
                       A + (size_t)(bm + ar) * K + k0 + seg * 8);
        }
        #pragma unroll
        for (int p = 0; p < 4; p++) {
            int idx = tid + p * 128;
            int br = idx >> 5, seg = idx & 31;
            CP_ASYNC16(smb + (bw + br * 136 + seg * 4) * 4,
                       B2 + (size_t)((k0 >> 1) + br) * (2 * N) + 2 * bn + seg * 8);
        }
        asm volatile("cp.async.commit_group;\n");
    };

    const int nk = K / 32;
    loadAB(0, 0);
    loadAB(1, 32);

    int cur = 0, nxt = 2;
    for (int kb = 0; kb < nk; kb++) {
        if (kb + 1 < nk) {
            asm volatile("cp.async.wait_group 1;\n");
        } else {
            asm volatile("cp.async.wait_group 0;\n");
        }
        __syncthreads();
        if (kb + 2 < nk) loadAB(nxt, (kb + 2) * 32);

        const unsigned* Ab = sm + cur * GSTG_W;
        const unsigned* Bb = Ab + GA_W;
        #pragma unroll
        for (int ks = 0; ks < 2; ks++) {
            unsigned a[4][4], b[8][2];
            #pragma unroll
            for (int mt = 0; mt < 4; mt++) {
                int r0 = wm * 64 + mt * 16;
                a[mt][0] = Ab[(r0 + g)     * 20 + 8 * ks + tg];
                a[mt][1] = Ab[(r0 + g + 8) * 20 + 8 * ks + tg];
                a[mt][2] = Ab[(r0 + g)     * 20 + 8 * ks + tg + 4];
                a[mt][3] = Ab[(r0 + g + 8) * 20 + 8 * ks + tg + 4];
            }
            #pragma unroll
            for (int nt = 0; nt < 8; nt++) {
                int col = wn * 64 + nt * 8 + g;
                b[nt][0] = Bb[(8 * ks + tg)     * 136 + col];
                b[nt][1] = Bb[(8 * ks + tg + 4) * 136 + col];
            }
            #pragma unroll
            for (int mt = 0; mt < 4; mt++)
                #pragma unroll
                for (int nt = 0; nt < 8; nt++)
                    mma_f16(c[mt][nt][0], c[mt][nt][1], c[mt][nt][2], c[mt][nt][3],
                            a[mt][0], a[mt][1], a[mt][2], a[mt][3],
                            b[nt][0], b[nt][1]);
        }
        cur = (cur == 2) ? 0 : cur + 1;
        nxt = (nxt == 2) ? 0 : nxt + 1;
    }

    #pragma unroll
    for (int mt = 0; mt < 4; mt++) {
        int r0 = bm + wm * 64 + mt * 16 + g;
        #pragma unroll
        for (int nt = 0; nt < 8; nt++) {
            int col = bn + wn * 64 + nt * 8 + 2 * tg;
            float v00 = c[mt][nt][0], v01 = c[mt][nt][1];
            float v10 = c[mt][nt][2], v11 = c[mt][nt][3];
            if (mode == 0) {
                float* C = (float*)Cv;
                float b0 = bias ? bias[col] : 0.f, b1 = bias ? bias[col + 1] : 0.f;
                *(float2*)(C + (size_t)r0 * N + col)       = make_float2(v00 + b0, v01 + b1);
                *(float2*)(C + (size_t)(r0 + 8) * N + col) = make_float2(v10 + b0, v11 + b1);
            } else if (col < 2048) {
                *(unsigned*)&g_qk[(size_t)r0 * 2048 + col]       = pack_h2(v00, v01);
                *(unsigned*)&g_qk[(size_t)(r0 + 8) * 2048 + col] = pack_h2(v10, v11);
            } else {
                int d = col - 2048;
                size_t vb0 = (size_t)(r0 >> 1) * 2048 + 2 * d + (r0 & 1);
                g_v[vb0]     = __float2half_rn(v00);
                g_v[vb0 + 2] = __float2half_rn(v01);
                size_t vb1 = (size_t)((r0 + 8) >> 1) * 2048 + 2 * d + ((r0 + 8) & 1);
                g_v[vb1]     = __float2half_rn(v10);
                g_v[vb1 + 2] = __float2half_rn(v11);
            }
        }
    }
}

// ---------------------------------------------------------------------------
// fp16 flash body — 128 threads, 4 warps of 32 q-rows, 64-key tiles.
// K stride 36 words; V stride 72 words (bank-clean); Ps 128x36.
// ---------------------------------------------------------------------------
#define FK_W 2304                  /* 64 x 36 */
#define FV_W 2304                  /* 32 x 72 */
#define FVS_BASE 4608
#define FPS_BASE 9216
#define FLASH_SMEM_W 13824         /* 55296 B */

__device__ __forceinline__ void flash_body(int qt, int b, int h, unsigned* sm) {
    const int tid = threadIdx.x;
    const int wid = tid >> 5, lane = tid & 31;
    const int g = lane >> 2, tg = lane & 3;
    const int qr = wid * 32;
    const size_t base = (size_t)b * SEQ;
    const size_t bv = (size_t)b * (SEQ / 2);
    const int ct0 = b * 16;
    const unsigned smb = (unsigned)__cvta_generic_to_shared(sm);
    unsigned* Ks = sm;
    unsigned* Vs = sm + FVS_BASE;
    unsigned* Ps = sm + FPS_BASE;   // doubles as Q stage

    // ---- Q stage ----
    waitcnt(&g_cnt1[ct0 + qt], 24);
    #pragma unroll
    for (int p = 0; p < 8; p++) {
        int idx = tid + p * 128;
        int row = idx >> 3, seg = idx & 7;
        CP_ASYNC16(smb + (FPS_BASE + row * 36 + seg * 4) * 4,
                   g_qk + (base + qt * 128 + row) * 2048 + h * DHEAD + seg * 8);
    }
    asm volatile("cp.async.commit_group;\n");
    asm volatile("cp.async.wait_group 0;\n");
    __syncthreads();

    unsigned qf[4][2][4];
    {
        const float QS = 0.125f * 1.4426950408889634f;
        #pragma unroll
        for (int ks = 0; ks < 4; ks++)
            #pragma unroll
            for (int mt = 0; mt < 2; mt++) {
                const int r0 = (qr + mt * 16 + g) * 36, r1 = r0 + 8 * 36;
                #pragma unroll
                for (int j = 0; j < 4; j++) {
                    int idx = ((j & 1) ? r1 : r0) + 8 * ks + tg + ((j >> 1) ? 4 : 0);
                    float2 f = up_h2(Ps[idx]);
                    qf[ks][mt][j] = pack_h2(f.x * QS, f.y * QS);
                }
            }
    }

    auto loadKV = [&](int buf, int kt) {
        #pragma unroll
        for (int p = 0; p < 4; p++) {
            int idx = tid + p * 128;
            int row = idx >> 3, seg = idx & 7;
            CP_ASYNC16(smb + (buf * FK_W + row * 36 + seg * 4) * 4,
                       g_qk + (base + kt * 64 + row) * 2048 + 1024 + h * DHEAD + seg * 8);
        }
        #pragma unroll
        for (int p = 0; p < 4; p++) {
            int idx = tid + p * 128;
            int rp = idx >> 4, seg = idx & 15;
            CP_ASYNC16(smb + (FVS_BASE + buf * FV_W + rp * 72 + seg * 4) * 4,
                       g_v + (bv + kt * 32 + rp) * 2048 + h * 128 + seg * 8);
        }
        asm volatile("cp.async.commit_group;\n");
    };

    int kvw = -1;
    auto wait_kv = [&](int j) {
        if (j > kvw) { waitcnt(&g_cnt1[ct0 + j], 24); kvw = j; }
    };

    const float NEG = -3.0e38f;
    float m[2][2] = {{NEG, NEG}, {NEG, NEG}}, l[2][2] = {};
    float c[2][8][4] = {};

    const int NT = SEQ / 64;
    wait_kv(0);
    loadKV(0, 0);

    for (int kt = 0; kt < NT; kt++) {
        asm volatile("cp.async.wait_group 0;\n");
        __syncthreads();
        if (kt + 1 < NT) {
            wait_kv((kt + 1) >> 1);
            loadKV((kt + 1) & 1, kt + 1);
        }

        const unsigned* Kb = Ks + (kt & 1) * FK_W;
        const unsigned* Vb = Vs + (kt & 1) * FV_W;

        // ---- S = Q @ K^T (log2 domain); B-frags reused across 2 A-tiles ----
        float sc[2][8][4] = {};
        #pragma unroll
        for (int ks = 0; ks < 4; ks++) {
            unsigned bfr[8][2];
            #pragma unroll
            for (int nt = 0; nt < 8; nt++) {
                bfr[nt][0] = Kb[(nt * 8 + g) * 36 + 8 * ks + tg];
                bfr[nt][1] = Kb[(nt * 8 + g) * 36 + 8 * ks + tg + 4];
            }
            #pragma unroll
            for (int mt = 0; mt < 2; mt++)
                #pragma unroll
                for (int nt = 0; nt < 8; nt++)
                    mma_f16(sc[mt][nt][0], sc[mt][nt][1], sc[mt][nt][2], sc[mt][nt][3],
                            qf[ks][mt][0], qf[ks][mt][1], qf[ks][mt][2], qf[ks][mt][3],
                            bfr[nt][0], bfr[nt][1]);
        }

        // ---- online softmax with running max ----
        #pragma unroll
        for (int mt = 0; mt < 2; mt++)
            #pragma unroll
            for (int rh = 0; rh < 2; rh++) {
                float mtv = NEG;
                #pragma unroll
                for (int nt = 0; nt < 8; nt++)
                    mtv = fmaxf(mtv, fmaxf(sc[mt][nt][2 * rh], sc[mt][nt][2 * rh + 1]));
                mtv = fmaxf(mtv, __shfl_xor_sync(0xffffffffu, mtv, 1));
                mtv = fmaxf(mtv, __shfl_xor_sync(0xffffffffu, mtv, 2));
                float mn = fmaxf(m[mt][rh], mtv);
                float fs = fex2(m[mt][rh] - mn);
                float rs = 0.f;
                int prow = (qr + mt * 16 + g + 8 * rh) * 36;
                #pragma unroll
                for (int nt = 0; nt < 8; nt++) {
                    unsigned ph = pack_h2(fex2(sc[mt][nt][2 * rh] - mn),
                                          fex2(sc[mt][nt][2 * rh + 1] - mn));
                    float2 pf = up_h2(ph);
                    rs += pf.x + pf.y;
                    Ps[prow + nt * 4 + tg] = ph;
                }
                rs += __shfl_xor_sync(0xffffffffu, rs, 1);
                rs += __shfl_xor_sync(0xffffffffu, rs, 2);
                l[mt][rh] = l[mt][rh] * fs + rs;
                m[mt][rh] = mn;
                #pragma unroll
                for (int nt = 0; nt < 8; nt++) {
                    c[mt][nt][2 * rh]     *= fs;
                    c[mt][nt][2 * rh + 1] *= fs;
                }
            }
        __syncwarp();

        // ---- O += P @ V; V-frags reused across 2 A-tiles ----
        #pragma unroll
        for (int ks = 0; ks < 4; ks++) {
            unsigned bfr[8][2], a[2][4];
            #pragma unroll
            for (int nt = 0; nt < 8; nt++) {
                bfr[nt][0] = Vb[(8 * ks + tg)     * 72 + nt * 8 + g];
                bfr[nt][1] = Vb[(8 * ks + tg + 4) * 72 + nt * 8 + g];
            }
            #pragma unroll
            for (int mt = 0; mt < 2; mt++) {
                int r0 = (qr + mt * 16 + g) * 36, r1 = r0 + 8 * 36;
                a[mt][0] = Ps[r0 + 8 * ks + tg];
                a[mt][1] = Ps[r1 + 8 * ks + tg];
                a[mt][2] = Ps[r0 + 8 * ks + tg + 4];
                a[mt][3] = Ps[r1 + 8 * ks + tg + 4];
            }
            #pragma unroll
            for (int mt = 0; mt < 2; mt++)
                #pragma unroll
                for (int nt = 0; nt < 8; nt++)
                    mma_f16(c[mt][nt][0], c[mt][nt][1], c[mt][nt][2], c[mt][nt][3],
                            a[mt][0], a[mt][1], a[mt][2], a[mt][3],
                            bfr[nt][0], bfr[nt][1]);
        }
        __syncwarp();
    }

    // ---- epilogue ----
    #pragma unroll
    for (int mt = 0; mt < 2; mt++) {
        const float i0 = 1.f / l[mt][0], i1 = 1.f / l[mt][1];
        size_t r0 = (base + qt * 128 + qr + mt * 16 + g) * (size_t)DIMN + h * DHEAD;
        size_t r1 = r0 + 8 * (size_t)DIMN;
        #pragma unroll
        for (int nt = 0; nt < 8; nt++) {
            int col = nt * 8 + 2 * tg;
            *(unsigned*)&g_attn[r0 + col] = pack_h2(c[mt][nt][0] * i0, c[mt][nt][1] * i0);
            *(unsigned*)&g_attn[r1 + col] = pack_h2(c[mt][nt][2] * i1, c[mt][nt][3] * i1);
        }
    }
}

// ---------------------------------------------------------------------------
// Fused kernel (R13 dispatch), 128-thread CTAs, 2 CTAs/SM.
// ---------------------------------------------------------------------------
#define G1 1536
#define G2 1024
#define G3 512
#define FUSED_SMEM 56832

__global__ __launch_bounds__(128, 2) void fused_kernel(const float* __restrict__ b_out,
                                                       float* __restrict__ out) {
    extern __shared__ unsigned smw[];
    cudaGridDependencySynchronize();
    cudaTriggerProgrammaticLaunchCompletion();

    const int bid = blockIdx.x;
    const int tid = threadIdx.x;

    if (bid < G1) {
        const int bm = (bid / 24) * 128, bn = (bid % 24) * 128;
        gemm_body(g_xn, g_wq2, nullptr, nullptr, QKV_N, DIMN, 1, bm, bn, smw);
        __syncthreads();
        if (tid == 0) { __threadfence(); atomicAdd(&g_cnt1[bm >> 7], 1); }
    } else if (bid < G1 + G2) {
        const int f = bid - G1;
        const int b = f >> 8, r = f & 255, qt = r >> 4, h = r & 15;
        flash_body(qt, b, h, smw);
        __syncthreads();
        if (tid == 0) { __threadfence(); atomicAdd(&g_cnt2[b * 16 + qt], 1); }
    } else {
        const int z = bid - G1 - G2;
        const int bm = (z >> 3) * 128, bn = (z & 7) * 128;
        waitcnt(&g_cnt2[bm >> 7], 16);
        gemm_body(g_attn, g_wo2, b_out, out, DIMN, DIMN, 0, bm, bn, smw);
    }
}

// ---------------------------------------------------------------------------
extern "C" void kernel_launch(void* const* d_in, const int* in_sizes, int n_in,
                              void* d_out, int out_size)
{
    const float* x      = (const float*)d_in[0];
    const float* gamma  = (const float*)d_in[1];
    const float* beta   = (const float*)d_in[2];
    const float* w_qkv  = (const float*)d_in[3];
    const float* w_out  = (const float*)d_in[4];
    const float* b_out  = (const float*)d_in[5];
    float* out = (float*)d_out;

    cudaFuncSetAttribute(fused_kernel, cudaFuncAttributeMaxDynamicSharedMemorySize,
                         FUSED_SMEM);

    cudaLaunchAttribute pdl[1];
    pdl[0].id = cudaLaunchAttributeProgrammaticStreamSerialization;
    pdl[0].val.programmaticStreamSerializationAllowed = 1;

    prep_kernel<<<PREP_BLKS, 256>>>(w_qkv, w_out, x, gamma, beta);

    cudaLaunchConfig_t cfg = {};
    cfg.gridDim = dim3(G1 + G2 + G3);
    cfg.blockDim = dim3(128);
    cfg.dynamicSmemBytes = FUSED_SMEM;
    cfg.stream = 0;
    cfg.attrs = pdl;
    cfg.numAttrs = 1;
    cudaLaunchKernelEx(&cfg, fused_kernel, b_out, out);
}